// round 3
// baseline (speedup 1.0000x reference)
#include <cuda_runtime.h>
#include <cuda_fp16.h>
#include <cstdint>
#include <cstddef>

#define DI __device__ __forceinline__

// ---------------- problem constants ----------------
constexpr int MROWS = 4096;
constexpr int KDIM  = 2048;           // K == N for every GEMM
constexpr int BM = 128, BN = 128, BK = 32;
constexpr int NK = KDIM / BK;         // 64 k-chunks
constexpr int STAGES = 5;
constexpr uint32_t STAGE_BYTES = 4u * 8192u;          // Ah,Al,Bh,Bl tiles (8KB each)
constexpr uint32_t SMEM_DYN = STAGES * STAGE_BYTES + 128;
constexpr int MTILES = MROWS / BM;    // 32
constexpr int NTILES = KDIM / BN;     // 16

// ---------------- device scratch (allocation-free rule) ----------------
__device__ __half g_Ah[2][(size_t)MROWS * KDIM];
__device__ __half g_Al[2][(size_t)MROWS * KDIM];
__device__ __half g_Bh[3][(size_t)KDIM * KDIM];
__device__ __half g_Bl[3][(size_t)KDIM * KDIM];

// ---------------- helpers ----------------
DI uint32_t s2u(const void* p) {
    uint32_t r;
    asm("{ .reg .u64 t; cvta.to.shared.u64 t, %1; cvt.u32.u64 %0, t; }" : "=r"(r) : "l"(p));
    return r;
}
DI void cp16(uint32_t dst, const void* src) {
    asm volatile(
        "{ .reg .u64 g; cvta.to.global.u64 g, %1; cp.async.cg.shared.global [%0], [g], 16; }"
        :: "r"(dst), "l"(src) : "memory");
}
DI void cp_commit() { asm volatile("cp.async.commit_group;" ::: "memory"); }
DI void cp_wait3()  { asm volatile("cp.async.wait_group 3;" ::: "memory"); }

#define LDM4(R0, R1, R2, R3, ADDR) \
    asm volatile("ldmatrix.sync.aligned.m8n8.x4.shared.b16 {%0,%1,%2,%3}, [%4];" \
                 : "=r"(R0), "=r"(R1), "=r"(R2), "=r"(R3) : "r"(ADDR))

#define MMA(C, A, B0, B1) \
    asm volatile("mma.sync.aligned.m16n8k16.row.col.f32.f16.f16.f32 " \
                 "{%0,%1,%2,%3},{%4,%5,%6,%7},{%8,%9},{%0,%1,%2,%3};" \
                 : "+f"((C)[0]), "+f"((C)[1]), "+f"((C)[2]), "+f"((C)[3]) \
                 : "r"((A)[0]), "r"((A)[1]), "r"((A)[2]), "r"((A)[3]), "r"(B0), "r"(B1))

DI void split1(float f, __half& h, __half& l) {
    h = __float2half_rn(f);
    l = __float2half_rn(f - __half2float(h));
}

// ============ prologue: pack concat(x0,x1) -> fp16 hi/lo planes ============
__global__ void pack_x_kernel(const float* __restrict__ x0, const float* __restrict__ x1) {
    int id = blockIdx.x * 256 + threadIdx.x;       // 2M threads, one float4 each
    int m = id >> 9;
    int c4 = (id & 511) * 4;
    const float* s = (c4 < 1024) ? (x0 + (size_t)m * 1024 + c4)
                                 : (x1 + (size_t)m * 1024 + (c4 - 1024));
    float4 v = *(const float4*)s;
    __half h0, h1, h2, h3, l0, l1, l2, l3;
    split1(v.x, h0, l0); split1(v.y, h1, l1);
    split1(v.z, h2, l2); split1(v.w, h3, l3);
    size_t off = (size_t)m * KDIM + c4;
    *(__half2*)(&g_Ah[0][off])     = __halves2half2(h0, h1);
    *(__half2*)(&g_Ah[0][off + 2]) = __halves2half2(h2, h3);
    *(__half2*)(&g_Al[0][off])     = __halves2half2(l0, l1);
    *(__half2*)(&g_Al[0][off + 2]) = __halves2half2(l2, l3);
}

// ============ prologue: W[k][n] -> Bt[n][k] fp16 hi/lo planes ============
__global__ void pack_w_kernel(const float* __restrict__ W0, const float* __restrict__ W1,
                              const float* __restrict__ W2) {
    __shared__ float s[32][33];
    int w = blockIdx.z;
    const float* W = (w == 0) ? W0 : ((w == 1) ? W1 : W2);
    int n0 = blockIdx.x * 32, k0 = blockIdx.y * 32;
    int tx = threadIdx.x, ty = threadIdx.y;  // (32, 8)
#pragma unroll
    for (int i = 0; i < 4; i++)
        s[ty + i * 8][tx] = W[(size_t)(k0 + ty + i * 8) * KDIM + n0 + tx];
    __syncthreads();
#pragma unroll
    for (int i = 0; i < 4; i++) {
        float v = s[tx][ty + i * 8];           // (k_local=tx, n_local=ty+8i)
        __half h, l;
        split1(v, h, l);
        size_t off = (size_t)(n0 + ty + i * 8) * KDIM + k0 + tx;
        g_Bh[w][off] = h;
        g_Bl[w][off] = l;
    }
}

// ============ main GEMM: C = A @ Bt^T via fp16-split 3-product mma.sync ============
template <bool PACK>
__global__ void __launch_bounds__(256, 1)
gemm_kernel(int aset, int wsel, int oset, float* __restrict__ out) {
    extern __shared__ uint8_t smem[];
    uint32_t tiles = (s2u(smem) + 127u) & ~127u;

    const __half* Ah = g_Ah[aset];
    const __half* Al = g_Al[aset];
    const __half* Bh = g_Bh[wsel];
    const __half* Bl = g_Bl[wsel];
    __half* Oh = g_Ah[oset];
    __half* Ol = g_Al[oset];

    int tid = threadIdx.x, lane = tid & 31, wid = tid >> 5;
    int warp_m = wid >> 1, warp_n = wid & 1;            // 4 x 2 warp grid
    int mtile = blockIdx.x & 31, ntile = blockIdx.x >> 5;

    const size_t arow = (size_t)mtile * BM * KDIM;
    const size_t brow = (size_t)ntile * BN * KDIM;

    float c[2][8][4];
#pragma unroll
    for (int a = 0; a < 2; a++)
#pragma unroll
        for (int b = 0; b < 8; b++)
#pragma unroll
            for (int d = 0; d < 4; d++) c[a][b][d] = 0.f;

    // per-chunk loader: 4 planes x 128 rows x 64B, XOR-swizzled 16B chunks
    auto load_chunk = [&](int chunk) {
        if (chunk < NK) {
            uint32_t st = tiles + (uint32_t)(chunk % STAGES) * STAGE_BYTES;
            int kc0 = chunk * BK;
            int cc = tid & 3;
#pragma unroll
            for (int p = 0; p < 8; p++) {
                int plane = p >> 1;
                int r = ((p & 1) << 6) + (tid >> 2);
                const __half* src;
                if (plane == 0)      src = Ah + arow + (size_t)r * KDIM + kc0 + cc * 8;
                else if (plane == 1) src = Al + arow + (size_t)r * KDIM + kc0 + cc * 8;
                else if (plane == 2) src = Bh + brow + (size_t)r * KDIM + kc0 + cc * 8;
                else                 src = Bl + brow + (size_t)r * KDIM + kc0 + cc * 8;
                uint32_t dst = st + (uint32_t)plane * 8192u + (uint32_t)r * 64u +
                               (uint32_t)((cc ^ ((r >> 1) & 3)) << 4);
                cp16(dst, src);
            }
        }
        cp_commit();
    };

#pragma unroll
    for (int c0 = 0; c0 < STAGES - 1; c0++) load_chunk(c0);

    // ldmatrix lane->row/chunk mapping (standard m16n8k16 fragment layouts)
    const int aR = warp_m * 32 + (lane & 7) + ((lane >> 3) & 1) * 8;
    const int aC = lane >> 4;
    const int bR = warp_n * 64 + (lane & 7) + ((lane >> 4) << 3);
    const int bC = (lane >> 3) & 1;

#pragma unroll 1
    for (int k = 0; k < NK; k++) {
        cp_wait3();
        __syncthreads();
        load_chunk(k + STAGES - 1);
        uint32_t st = tiles + (uint32_t)(k % STAGES) * STAGE_BYTES;
#pragma unroll
        for (int ks = 0; ks < 2; ks++) {
            uint32_t ah[2][4], al[2][4], bh[8][2], bl[8][2];
#pragma unroll
            for (int tm = 0; tm < 2; tm++) {
                int row = aR + tm * 16;
                uint32_t cidx = (uint32_t)((ks * 2 + aC) ^ ((row >> 1) & 3));
                uint32_t ad = st + (uint32_t)row * 64u + (cidx << 4);
                LDM4(ah[tm][0], ah[tm][1], ah[tm][2], ah[tm][3], ad);
                LDM4(al[tm][0], al[tm][1], al[tm][2], al[tm][3], ad + 8192u);
            }
#pragma unroll
            for (int p = 0; p < 4; p++) {
                int row = bR + p * 16;
                uint32_t cidx = (uint32_t)((ks * 2 + bC) ^ ((row >> 1) & 3));
                uint32_t bd = st + 16384u + (uint32_t)row * 64u + (cidx << 4);
                uint32_t r0, r1, r2, r3;
                LDM4(r0, r1, r2, r3, bd);
                bh[2 * p][0] = r0; bh[2 * p][1] = r1;
                bh[2 * p + 1][0] = r2; bh[2 * p + 1][1] = r3;
                LDM4(r0, r1, r2, r3, bd + 8192u);
                bl[2 * p][0] = r0; bl[2 * p][1] = r1;
                bl[2 * p + 1][0] = r2; bl[2 * p + 1][1] = r3;
            }
#pragma unroll
            for (int tm = 0; tm < 2; tm++)
#pragma unroll
                for (int tn = 0; tn < 8; tn++) {
                    MMA(c[tm][tn], ah[tm], bh[tn][0], bh[tn][1]);
                    MMA(c[tm][tn], al[tm], bh[tn][0], bh[tn][1]);
                    MMA(c[tm][tn], ah[tm], bl[tn][0], bl[tn][1]);
                }
        }
    }

    // ---- epilogue ----
    int r0 = mtile * BM + warp_m * 32 + (lane >> 2);
    int col0 = ntile * BN + warp_n * 64 + (lane & 3) * 2;
#pragma unroll
    for (int tm = 0; tm < 2; tm++)
#pragma unroll
        for (int tn = 0; tn < 8; tn++) {
            int r = r0 + tm * 16, cc = col0 + tn * 8;
            float* v = c[tm][tn];
            if (PACK) {
#pragma unroll
                for (int h = 0; h < 2; h++) {
                    size_t off = (size_t)(r + h * 8) * KDIM + cc;
                    __half h0, h1, l0, l1;
                    split1(v[2 * h], h0, l0);
                    split1(v[2 * h + 1], h1, l1);
                    *(__half2*)(Oh + off) = __halves2half2(h0, h1);
                    *(__half2*)(Ol + off) = __halves2half2(l0, l1);
                }
            } else {
                *(float2*)(out + (size_t)r * KDIM + cc) = make_float2(v[0], v[1]);
                *(float2*)(out + (size_t)(r + 8) * KDIM + cc) = make_float2(v[2], v[3]);
            }
        }
}

// ---------------- launch ----------------
extern "C" void kernel_launch(void* const* d_in, const int* in_sizes, int n_in,
                              void* d_out, int out_size) {
    const float* x0 = (const float*)d_in[0];
    const float* x1 = (const float*)d_in[1];
    const float* W0 = (const float*)d_in[2];
    const float* W1 = (const float*)d_in[3];
    const float* W2 = (const float*)d_in[4];
    float* out = (float*)d_out;

    cudaFuncSetAttribute(gemm_kernel<true>,
                         cudaFuncAttributeMaxDynamicSharedMemorySize, SMEM_DYN);
    cudaFuncSetAttribute(gemm_kernel<false>,
                         cudaFuncAttributeMaxDynamicSharedMemorySize, SMEM_DYN);

    pack_x_kernel<<<8192, 256>>>(x0, x1);
    pack_w_kernel<<<dim3(64, 64, 3), dim3(32, 8)>>>(W0, W1, W2);
    // chain: set0 -> set1 -> set0 -> out
    gemm_kernel<true ><<<MTILES * NTILES, 256, SMEM_DYN>>>(0, 0, 1, nullptr);
    gemm_kernel<true ><<<MTILES * NTILES, 256, SMEM_DYN>>>(1, 1, 0, nullptr);
    gemm_kernel<false><<<MTILES * NTILES, 256, SMEM_DYN>>>(0, 2, 0, out);
}